// round 1
// baseline (speedup 1.0000x reference)
#include <cuda_runtime.h>
#include <math.h>

#define S_DIM 8192
#define B_DIM 32
#define H_DIM 256
#define NCHUNK 32
#define CS (S_DIM / NCHUNK)      // 256 rows per chunk
#define WARPS 8
#define SPW (CS / WARPS)         // 32 rows per warp

// Scratch for split-S partials (no-alloc rule: __device__ globals)
__device__ float g_num[NCHUNK][B_DIM][H_DIM];  // unnormalized numerators
__device__ float g_m[NCHUNK][B_DIM];           // per-chunk running max
__device__ float g_l[NCHUNK][B_DIM];           // per-chunk denom (rel. to g_m)

__global__ __launch_bounds__(256) void attn_partial(
    const float* __restrict__ X,     // [S, B, H]
    const float* __restrict__ Hid)   // [B, H]
{
    const int chunk = blockIdx.x;
    const int b     = blockIdx.y;
    const int tid   = threadIdx.x;
    const int w     = tid >> 5;
    const int lane  = tid & 31;

    // Each lane owns 8 h-values: h = lane*8 .. lane*8+7
    const float4* h4 = reinterpret_cast<const float4*>(Hid + b * H_DIM) + lane * 2;
    const float4 hv0 = h4[0];
    const float4 hv1 = h4[1];

    float m = -1e30f, l = 0.0f;
    float acc[8];
#pragma unroll
    for (int j = 0; j < 8; j++) acc[j] = 0.0f;

    const int s0 = chunk * CS + w * SPW;
    const float* Xb = X + (size_t)b * H_DIM;

#pragma unroll 4
    for (int i = 0; i < SPW; i++) {
        const int s = s0 + i;
        const float4* x4 =
            reinterpret_cast<const float4*>(Xb + (size_t)s * (B_DIM * H_DIM)) + lane * 2;
        const float4 a0 = x4[0];
        const float4 a1 = x4[1];

        // partial dot over this lane's 8 elements
        float p;
        p = a0.x * hv0.x;
        p = fmaf(a0.y, hv0.y, p);
        p = fmaf(a0.z, hv0.z, p);
        p = fmaf(a0.w, hv0.w, p);
        p = fmaf(a1.x, hv1.x, p);
        p = fmaf(a1.y, hv1.y, p);
        p = fmaf(a1.z, hv1.z, p);
        p = fmaf(a1.w, hv1.w, p);

        // butterfly reduce: every lane gets the full score
#pragma unroll
        for (int o = 16; o; o >>= 1)
            p += __shfl_xor_sync(0xFFFFFFFFu, p, o);

        // online softmax update
        const float mn   = fmaxf(m, p);
        const float corr = __expf(m - mn);   // 0 when m == -1e30
        const float wt   = __expf(p - mn);
        l = fmaf(l, corr, wt);
        acc[0] = fmaf(acc[0], corr, wt * a0.x);
        acc[1] = fmaf(acc[1], corr, wt * a0.y);
        acc[2] = fmaf(acc[2], corr, wt * a0.z);
        acc[3] = fmaf(acc[3], corr, wt * a0.w);
        acc[4] = fmaf(acc[4], corr, wt * a1.x);
        acc[5] = fmaf(acc[5], corr, wt * a1.y);
        acc[6] = fmaf(acc[6], corr, wt * a1.z);
        acc[7] = fmaf(acc[7], corr, wt * a1.w);
        m = mn;
    }

    // Combine the 8 warps' partials in shared memory
    __shared__ float sm[WARPS];
    __shared__ float sl[WARPS];
    __shared__ float sacc[WARPS][H_DIM];

    if (lane == 0) { sm[w] = m; sl[w] = l; }
#pragma unroll
    for (int j = 0; j < 8; j++) sacc[w][lane * 8 + j] = acc[j];
    __syncthreads();

    // thread tid owns output element h = tid
    float M = -1e30f;
#pragma unroll
    for (int ww = 0; ww < WARPS; ww++) M = fmaxf(M, sm[ww]);
    float num = 0.0f, den = 0.0f;
#pragma unroll
    for (int ww = 0; ww < WARPS; ww++) {
        const float e = __expf(sm[ww] - M);
        num = fmaf(e, sacc[ww][tid], num);
        den = fmaf(e, sl[ww], den);
    }
    g_num[chunk][b][tid] = num;
    if (tid == 0) { g_m[chunk][b] = M; g_l[chunk][b] = den; }
}

__global__ __launch_bounds__(256) void attn_reduce(float* __restrict__ out)
{
    const int b   = blockIdx.x;
    const int tid = threadIdx.x;   // h index

    __shared__ float sm[NCHUNK];
    __shared__ float sl[NCHUNK];
    if (tid < NCHUNK) {
        sm[tid] = g_m[tid][b];
        sl[tid] = g_l[tid][b];
    }
    __syncthreads();

    float M = -1e30f;
#pragma unroll
    for (int c = 0; c < NCHUNK; c++) M = fmaxf(M, sm[c]);

    float num = 0.0f, den = 0.0f;
#pragma unroll
    for (int c = 0; c < NCHUNK; c++) {
        const float e = __expf(sm[c] - M);
        num = fmaf(e, g_num[c][b][tid], num);
        den = fmaf(e, sl[c], den);
    }
    out[b * H_DIM + tid] = num / den;
}

extern "C" void kernel_launch(void* const* d_in, const int* in_sizes, int n_in,
                              void* d_out, int out_size)
{
    const float* X   = (const float*)d_in[0];   // [S, B, H]
    const float* Hid = (const float*)d_in[1];   // [1, B, H] -> [B, H]
    float* out = (float*)d_out;                 // [B, H]

    dim3 grid1(NCHUNK, B_DIM);
    attn_partial<<<grid1, 256>>>(X, Hid);
    attn_reduce<<<B_DIM, 256>>>(out);
}